// round 2
// baseline (speedup 1.0000x reference)
#include <cuda_runtime.h>
#include <stdint.h>

// Problem constants
#define BB 32
#define SS 2048
#define DD 128
#define BQ 64
#define BK 64
#define NTH 256

// ---------------------------------------------------------------------------
// Dropout mask: bit-exact replication of
//   jax.random.bernoulli(jax.random.key(42), 0.7, (32,2048,2048))
// with jax_threefry_partitionable=True (default since jax 0.4.36):
//   element i: (x0,x1) = threefry2x32(key=(0,42), ctr=(hi32(i), lo32(i)))
//   bits      = x0 ^ x1           (32-bit fold of the 64-bit hash output)
//   keep     <=> (bits >> 9) < 5872026  <=> bits < (5872026u << 9)
// For n = 2^27 elements, hi32(i) == 0 always.
// Stored as a bit array: word w covers elements [32w, 32w+32).
// ---------------------------------------------------------------------------
__device__ uint32_t g_mask[1u << 22];   // 2^27 bits = 16 MB

__device__ __forceinline__ uint32_t rotl32(uint32_t x, int r) {
    return __funnelshift_l(x, x, r);
}

#define TF_ROUND(r) do { x0 += x1; x1 = rotl32(x1, (r)); x1 ^= x0; } while (0)

// threefry2x32 with key (0, 42); returns x0 ^ x1
__device__ __forceinline__ uint32_t threefry_fold_0_42(uint32_t c0, uint32_t c1) {
    const uint32_t ks0 = 0u, ks1 = 42u, ks2 = 42u ^ 0x1BD11BDAu;
    uint32_t x0 = c0 + ks0;
    uint32_t x1 = c1 + ks1;
    TF_ROUND(13); TF_ROUND(15); TF_ROUND(26); TF_ROUND(6);
    x0 += ks1; x1 += ks2 + 1u;
    TF_ROUND(17); TF_ROUND(29); TF_ROUND(16); TF_ROUND(24);
    x0 += ks2; x1 += ks0 + 2u;
    TF_ROUND(13); TF_ROUND(15); TF_ROUND(26); TF_ROUND(6);
    x0 += ks0; x1 += ks1 + 3u;
    TF_ROUND(17); TF_ROUND(29); TF_ROUND(16); TF_ROUND(24);
    x0 += ks1; x1 += ks2 + 4u;
    TF_ROUND(13); TF_ROUND(15); TF_ROUND(26); TF_ROUND(6);
    x0 += ks2; x1 += ks0 + 5u;
    return x0 ^ x1;
}

__global__ void __launch_bounds__(NTH) mask_kernel() {
    const uint32_t TH = 3006477312u;              // 5872026 << 9
    uint32_t t = blockIdx.x * NTH + threadIdx.x;  // word index, t < 2^22
    uint32_t base = t << 5;                       // element index of bit 0
    uint32_t w = 0u;
#pragma unroll 8
    for (int j = 0; j < 32; j++) {
        uint32_t bits = threefry_fold_0_42(0u, base + (uint32_t)j);
        w |= (bits < TH) ? (1u << j) : 0u;
    }
    g_mask[t] = w;
}

// ---------------------------------------------------------------------------
// fp32 flash attention with per-batch scale + post-softmax dropout.
// Grid: (Sq/BQ, B). 256 threads: 16x16 thread tile.
// gemm1: thread (ty,tx) owns S[4ty..4ty+3][4tx..4tx+3]
// gemm2: thread (ty,tx) owns O[4ty..4ty+3][8tx..8tx+7]
// ---------------------------------------------------------------------------
#define QK_PAD 68     // 64 + 4, row stride (floats) of transposed Q/K and P
#define V_PAD 132     // 128 + 4

#define SMEM_FLOATS (2 * 128 * QK_PAD + 64 * V_PAD + 64 * QK_PAD)
#define SMEM_BYTES (SMEM_FLOATS * 4)

__global__ void __launch_bounds__(NTH, 1) attn_kernel(
    const float* __restrict__ q, const float* __restrict__ k,
    const float* __restrict__ v, const float* __restrict__ scale,
    float* __restrict__ out) {
    extern __shared__ float sm[];
    float* Qt = sm;                       // [128][QK_PAD]  Qt[d][row]
    float* Kt = Qt + 128 * QK_PAD;        // [128][QK_PAD]  Kt[d][key]
    float* Vs = Kt + 128 * QK_PAD;        // [64][V_PAD]    Vs[key][d]
    float* Pm = Vs + 64 * V_PAD;          // [64][QK_PAD]   masked P

    const int tid = threadIdx.x;
    const int tx = tid & 15;
    const int ty = tid >> 4;
    const int b = blockIdx.y;
    const int q0 = blockIdx.x * BQ;

    const float sc = scale[b];
    const float* qb = q + ((size_t)b * SS + q0) * DD;
    const float* kb = k + (size_t)b * SS * DD;
    const float* vb = v + (size_t)b * SS * DD;

    // ---- load Q tile, transposed ----
#pragma unroll
    for (int it = 0; it < 8; it++) {
        int f = tid + it * NTH;           // 2048 float4
        int row = f >> 5, c4 = f & 31;
        float4 x = *(const float4*)(qb + row * DD + c4 * 4);
        Qt[(c4 * 4 + 0) * QK_PAD + row] = x.x;
        Qt[(c4 * 4 + 1) * QK_PAD + row] = x.y;
        Qt[(c4 * 4 + 2) * QK_PAD + row] = x.z;
        Qt[(c4 * 4 + 3) * QK_PAD + row] = x.w;
    }

    float m[4], l[4];
    float acc[4][8];
#pragma unroll
    for (int r = 0; r < 4; r++) {
        m[r] = -INFINITY;
        l[r] = 0.f;
#pragma unroll
        for (int c = 0; c < 8; c++) acc[r][c] = 0.f;
    }

    const float L2E = 1.4426950408889634f;

    for (int kt = 0; kt < SS / BK; kt++) {
        const int k0 = kt * BK;
        __syncthreads();   // previous iter's gemm2 done before overwriting K/V
        // ---- load K (transposed) and V tiles ----
#pragma unroll
        for (int it = 0; it < 8; it++) {
            int f = tid + it * NTH;
            int row = f >> 5, c4 = f & 31;
            float4 x = *(const float4*)(kb + (size_t)(k0 + row) * DD + c4 * 4);
            Kt[(c4 * 4 + 0) * QK_PAD + row] = x.x;
            Kt[(c4 * 4 + 1) * QK_PAD + row] = x.y;
            Kt[(c4 * 4 + 2) * QK_PAD + row] = x.z;
            Kt[(c4 * 4 + 3) * QK_PAD + row] = x.w;
            float4 y = *(const float4*)(vb + (size_t)(k0 + row) * DD + c4 * 4);
            *(float4*)(Vs + row * V_PAD + c4 * 4) = y;
        }
        __syncthreads();

        // ---- gemm1: S = Q K^T (4x4 per thread) ----
        float s[4][4];
#pragma unroll
        for (int r = 0; r < 4; r++)
#pragma unroll
            for (int c = 0; c < 4; c++) s[r][c] = 0.f;

#pragma unroll 4
        for (int kk = 0; kk < 128; kk++) {
            float4 qv = *(const float4*)(Qt + kk * QK_PAD + ty * 4);
            float4 kv = *(const float4*)(Kt + kk * QK_PAD + tx * 4);
            float qr[4] = {qv.x, qv.y, qv.z, qv.w};
            float kc[4] = {kv.x, kv.y, kv.z, kv.w};
#pragma unroll
            for (int r = 0; r < 4; r++)
#pragma unroll
                for (int c = 0; c < 4; c++) s[r][c] = fmaf(qr[r], kc[c], s[r][c]);
        }

        // ---- online softmax + dropout, write masked P ----
        float fr[4];
        const int j0 = (k0 + tx * 4) & 31;
        const uint32_t wcol = (uint32_t)(k0 + tx * 4) >> 5;
#pragma unroll
        for (int r = 0; r < 4; r++) {
            float sv[4];
#pragma unroll
            for (int c = 0; c < 4; c++) sv[c] = s[r][c] * sc;
            float rm = fmaxf(fmaxf(sv[0], sv[1]), fmaxf(sv[2], sv[3]));
#pragma unroll
            for (int o = 1; o < 16; o <<= 1)
                rm = fmaxf(rm, __shfl_xor_sync(0xffffffffu, rm, o, 16));
            float mn = fmaxf(m[r], rm);
            fr[r] = exp2f((m[r] - mn) * L2E);
            float e[4], rs = 0.f;
#pragma unroll
            for (int c = 0; c < 4; c++) { e[c] = exp2f((sv[c] - mn) * L2E); rs += e[c]; }
#pragma unroll
            for (int o = 1; o < 16; o <<= 1)
                rs += __shfl_xor_sync(0xffffffffu, rs, o, 16);
            l[r] = l[r] * fr[r] + rs;
            m[r] = mn;
            // dropout mask word for this (global row, 32-col block)
            const int gi = q0 + ty * 4 + r;
            const uint32_t wbase = (((uint32_t)b << 11) + (uint32_t)gi) << 6;
            uint32_t wrd = g_mask[wbase + wcol];
#pragma unroll
            for (int c = 0; c < 4; c++)
                Pm[(ty * 4 + r) * QK_PAD + tx * 4 + c] =
                    ((wrd >> (j0 + c)) & 1u) ? e[c] : 0.f;
        }
        __syncthreads();

        // ---- rescale accumulators, gemm2: O += P V ----
#pragma unroll
        for (int r = 0; r < 4; r++)
#pragma unroll
            for (int c = 0; c < 8; c++) acc[r][c] *= fr[r];

#pragma unroll 4
        for (int kk = 0; kk < 64; kk++) {
            float4 v0 = *(const float4*)(Vs + kk * V_PAD + tx * 8);
            float4 v1 = *(const float4*)(Vs + kk * V_PAD + tx * 8 + 4);
            float vv[8] = {v0.x, v0.y, v0.z, v0.w, v1.x, v1.y, v1.z, v1.w};
#pragma unroll
            for (int r = 0; r < 4; r++) {
                float p = Pm[(ty * 4 + r) * QK_PAD + kk];
#pragma unroll
                for (int c = 0; c < 8; c++) acc[r][c] = fmaf(p, vv[c], acc[r][c]);
            }
        }
    }

    // ---- epilogue: divide by (l * keep_p), write out ----
#pragma unroll
    for (int r = 0; r < 4; r++) {
        float inv = 1.f / (l[r] * 0.7f);
        int gr = q0 + ty * 4 + r;
        float* op = out + ((size_t)b * SS + gr) * DD + tx * 8;
        float4 o0, o1;
        o0.x = acc[r][0] * inv; o0.y = acc[r][1] * inv;
        o0.z = acc[r][2] * inv; o0.w = acc[r][3] * inv;
        o1.x = acc[r][4] * inv; o1.y = acc[r][5] * inv;
        o1.z = acc[r][6] * inv; o1.w = acc[r][7] * inv;
        *(float4*)(op) = o0;
        *(float4*)(op + 4) = o1;
    }
}

// ---------------------------------------------------------------------------
extern "C" void kernel_launch(void* const* d_in, const int* in_sizes, int n_in,
                              void* d_out, int out_size) {
    (void)in_sizes; (void)n_in; (void)out_size;
    const float* q = (const float*)d_in[0];
    const float* k = (const float*)d_in[1];
    const float* v = (const float*)d_in[2];
    const float* scale = (const float*)d_in[3];
    float* out = (float*)d_out;

    // one-time config (runs on the correctness call, before graph capture)
    static const bool _init = []() {
        cudaFuncSetAttribute(attn_kernel,
                             cudaFuncAttributeMaxDynamicSharedMemorySize,
                             SMEM_BYTES);
        return true;
    }();
    (void)_init;

    mask_kernel<<<(1 << 22) / NTH, NTH>>>();
    dim3 grid(SS / BQ, BB);
    attn_kernel<<<grid, NTH, SMEM_BYTES>>>(q, k, v, scale, out);
}

// round 4
// speedup vs baseline: 2.0243x; 2.0243x over previous
#include <cuda_runtime.h>
#include <stdint.h>
#include <math.h>

#define BB 32
#define SS 2048
#define DD 128
#define BQ 128
#define BK 64
#define NITER (SS / BK)
#define NTH 256

// ===========================================================================
// Dropout mask (partitionable threefry, verified bit-exact in R2)
// ===========================================================================
__device__ uint32_t g_mask[1u << 22];   // 2^27 bits

__device__ __forceinline__ uint32_t rotl32(uint32_t x, int r) {
    return __funnelshift_l(x, x, r);
}
#define TF_ROUND(r) do { x0 += x1; x1 = rotl32(x1, (r)); x1 ^= x0; } while (0)
__device__ __forceinline__ uint32_t threefry_fold_0_42(uint32_t c0, uint32_t c1) {
    const uint32_t ks0 = 0u, ks1 = 42u, ks2 = 42u ^ 0x1BD11BDAu;
    uint32_t x0 = c0 + ks0, x1 = c1 + ks1;
    TF_ROUND(13); TF_ROUND(15); TF_ROUND(26); TF_ROUND(6);
    x0 += ks1; x1 += ks2 + 1u;
    TF_ROUND(17); TF_ROUND(29); TF_ROUND(16); TF_ROUND(24);
    x0 += ks2; x1 += ks0 + 2u;
    TF_ROUND(13); TF_ROUND(15); TF_ROUND(26); TF_ROUND(6);
    x0 += ks0; x1 += ks1 + 3u;
    TF_ROUND(17); TF_ROUND(29); TF_ROUND(16); TF_ROUND(24);
    x0 += ks1; x1 += ks2 + 4u;
    TF_ROUND(13); TF_ROUND(15); TF_ROUND(26); TF_ROUND(6);
    x0 += ks2; x1 += ks0 + 5u;
    return x0 ^ x1;
}
__global__ void __launch_bounds__(NTH) mask_kernel() {
    const uint32_t TH = 3006477312u;              // 5872026 << 9
    uint32_t t = blockIdx.x * NTH + threadIdx.x;
    uint32_t base = t << 5;
    uint32_t w = 0u;
#pragma unroll 8
    for (int j = 0; j < 32; j++) {
        uint32_t bits = threefry_fold_0_42(0u, base + (uint32_t)j);
        w |= (bits < TH) ? (1u << j) : 0u;
    }
    g_mask[t] = w;
}

// ===========================================================================
// mma.sync tf32 helpers
// ===========================================================================
__device__ __forceinline__ void mma_tf32(float* c, const uint32_t* a,
                                         uint32_t b0, uint32_t b1) {
    asm volatile(
        "mma.sync.aligned.m16n8k8.row.col.f32.tf32.tf32.f32 "
        "{%0,%1,%2,%3}, {%4,%5,%6,%7}, {%8,%9}, {%0,%1,%2,%3};"
        : "+f"(c[0]), "+f"(c[1]), "+f"(c[2]), "+f"(c[3])
        : "r"(a[0]), "r"(a[1]), "r"(a[2]), "r"(a[3]), "r"(b0), "r"(b1));
}
__device__ __forceinline__ uint32_t tf32_rna(float x) {
    uint32_t u;
    asm("cvt.rna.tf32.f32 %0, %1;" : "=r"(u) : "f"(x));
    return u;
}
// exact-ish split: hi = truncate-to-19-bits, lo = truncate(x - hi)
__device__ __forceinline__ void split_tf32(float x, uint32_t& h, uint32_t& l) {
    uint32_t u = __float_as_uint(x);
    h = u & 0xffffe000u;
    float r = x - __uint_as_float(h);
    l = __float_as_uint(r) & 0xffffe000u;
}

// smem layout (bytes)
#define QS_STR 136
#define KS_STR 136
#define VS_STR 136
#define PS_STR 68
#define OFF_Q 0
#define OFF_K 69632              // 128*136*4
#define OFF_V 139264             // + 64*136*8
#define OFF_P 174080             // + 64*136*4
#define SMEM_BYTES 208896        // + 128*68*4

__global__ void __launch_bounds__(NTH) attn_mma(
    const float* __restrict__ q, const float* __restrict__ k,
    const float* __restrict__ v, const float* __restrict__ scale,
    float* __restrict__ out) {
    extern __shared__ char smem_raw[];
    float* Qs = (float*)(smem_raw + OFF_Q);           // [128][136] fp32 (scaled)
    uint2* Ks = (uint2*)(smem_raw + OFF_K);           // [64][136]  (hi,lo) tf32
    uint32_t* Vs = (uint32_t*)(smem_raw + OFF_V);     // [64][136]  tf32
    uint32_t* Ps = (uint32_t*)(smem_raw + OFF_P);     // [128][68]  tf32 (masked P)

    const int tid = threadIdx.x;
    const int lane = tid & 31;
    const int w = tid >> 5;
    const int g = lane >> 2;        // groupID
    const int tig = lane & 3;       // threadID in group
    const int wrow = w * 16;        // warp's row base within the 128-row tile
    const int b = blockIdx.y;
    const int q0 = blockIdx.x * BQ;

    const float* kb = k + (size_t)b * SS * DD;
    const float* vb = v + (size_t)b * SS * DD;

    // ---- prologue: load Q tile (scaled fp32) into smem ----
    {
        const float sc = scale[b];
        const float* qb = q + ((size_t)b * SS + q0) * DD;
#pragma unroll
        for (int i = 0; i < 16; i++) {
            int f = tid + i * NTH;          // 4096 float4
            int row = f >> 5, c4 = f & 31;
            float4 x = *(const float4*)(qb + row * DD + c4 * 4);
            float4 y = make_float4(x.x * sc, x.y * sc, x.z * sc, x.w * sc);
            *(float4*)(Qs + row * QS_STR + c4 * 4) = y;
        }
    }

    const int r0 = wrow + g;          // local rows this thread owns
    const int r1 = wrow + g + 8;
    const int gi0 = q0 + r0;          // global q rows
    const int gi1 = q0 + r1;
    const uint32_t mbase0 = (((uint32_t)b << 11) + (uint32_t)gi0) << 6;
    const uint32_t mbase1 = (((uint32_t)b << 11) + (uint32_t)gi1) << 6;
    const float L2E = 1.4426950408889634f;

    float m0 = -INFINITY, m1 = -INFINITY, l0 = 0.f, l1 = 0.f;
    float O[16][4];
#pragma unroll
    for (int nt = 0; nt < 16; nt++)
#pragma unroll
        for (int e = 0; e < 4; e++) O[nt][e] = 0.f;

    for (int t = 0; t < NITER; t++) {
        __syncthreads();   // all warps past gemm2(t-1) before K/V overwrite
        // ---- load K (split hi/lo) and V (tf32) tiles ----
        {
            const float* kt = kb + (size_t)t * BK * DD;
            const float* vt = vb + (size_t)t * BK * DD;
#pragma unroll
            for (int i = 0; i < 8; i++) {
                int f = tid + i * NTH;      // 2048 float4
                int row = f >> 5, c4 = f & 31;
                float4 x = *(const float4*)(kt + row * DD + c4 * 4);
                uint2* kd = Ks + row * KS_STR + c4 * 4;
                uint32_t h, lo;
                split_tf32(x.x, h, lo); kd[0] = make_uint2(h, lo);
                split_tf32(x.y, h, lo); kd[1] = make_uint2(h, lo);
                split_tf32(x.z, h, lo); kd[2] = make_uint2(h, lo);
                split_tf32(x.w, h, lo); kd[3] = make_uint2(h, lo);
                float4 y = *(const float4*)(vt + row * DD + c4 * 4);
                uint4 vv = make_uint4(tf32_rna(y.x), tf32_rna(y.y),
                                      tf32_rna(y.z), tf32_rna(y.w));
                *(uint4*)(Vs + row * VS_STR + c4 * 4) = vv;
            }
        }
        __syncthreads();

        // ---- gemm1: S[16,64] = Q[16,128] K^T, 3-pass tf32 split ----
        float S[8][4];
#pragma unroll
        for (int nt = 0; nt < 8; nt++)
#pragma unroll
            for (int e = 0; e < 4; e++) S[nt][e] = 0.f;

#pragma unroll 1
        for (int ks = 0; ks < 16; ks++) {
            const int kc = ks * 8 + tig;
            float qa0 = Qs[r0 * QS_STR + kc];
            float qa1 = Qs[r1 * QS_STR + kc];
            float qa2 = Qs[r0 * QS_STR + kc + 4];
            float qa3 = Qs[r1 * QS_STR + kc + 4];
            uint32_t ah[4], al[4];
            split_tf32(qa0, ah[0], al[0]);
            split_tf32(qa1, ah[1], al[1]);
            split_tf32(qa2, ah[2], al[2]);
            split_tf32(qa3, ah[3], al[3]);
            uint2 bb0[8], bb1[8];
#pragma unroll
            for (int nt = 0; nt < 8; nt++) {
                bb0[nt] = Ks[(nt * 8 + g) * KS_STR + kc];
                bb1[nt] = Ks[(nt * 8 + g) * KS_STR + kc + 4];
            }
#pragma unroll
            for (int nt = 0; nt < 8; nt++)
                mma_tf32(S[nt], ah, bb0[nt].x, bb1[nt].x);
#pragma unroll
            for (int nt = 0; nt < 8; nt++)
                mma_tf32(S[nt], ah, bb0[nt].y, bb1[nt].y);
#pragma unroll
            for (int nt = 0; nt < 8; nt++)
                mma_tf32(S[nt], al, bb0[nt].x, bb1[nt].x);
        }

        // ---- online softmax (rows r0, r1) + dropout mask + P store ----
        uint2 mwa = *(const uint2*)(g_mask + mbase0 + 2u * (uint32_t)t);
        uint2 mwb = *(const uint2*)(g_mask + mbase1 + 2u * (uint32_t)t);
        uint64_t mm0 = (uint64_t)mwa.x | ((uint64_t)mwa.y << 32);
        uint64_t mm1 = (uint64_t)mwb.x | ((uint64_t)mwb.y << 32);

        float rmax0 = -INFINITY, rmax1 = -INFINITY;
#pragma unroll
        for (int nt = 0; nt < 8; nt++) {
            rmax0 = fmaxf(rmax0, fmaxf(S[nt][0], S[nt][1]));
            rmax1 = fmaxf(rmax1, fmaxf(S[nt][2], S[nt][3]));
        }
        rmax0 = fmaxf(rmax0, __shfl_xor_sync(0xffffffffu, rmax0, 1));
        rmax0 = fmaxf(rmax0, __shfl_xor_sync(0xffffffffu, rmax0, 2));
        rmax1 = fmaxf(rmax1, __shfl_xor_sync(0xffffffffu, rmax1, 1));
        rmax1 = fmaxf(rmax1, __shfl_xor_sync(0xffffffffu, rmax1, 2));
        float mn0 = fmaxf(m0, rmax0), mn1 = fmaxf(m1, rmax1);
        float fr0 = exp2f((m0 - mn0) * L2E);
        float fr1 = exp2f((m1 - mn1) * L2E);

        float rs0 = 0.f, rs1 = 0.f;
#pragma unroll
        for (int nt = 0; nt < 8; nt++) {
            const int c = nt * 8 + 2 * tig;
            float e00 = exp2f((S[nt][0] - mn0) * L2E);
            float e01 = exp2f((S[nt][1] - mn0) * L2E);
            float e10 = exp2f((S[nt][2] - mn1) * L2E);
            float e11 = exp2f((S[nt][3] - mn1) * L2E);
            rs0 += e00 + e01;
            rs1 += e10 + e11;
            uint2 p0, p1;
            p0.x = ((mm0 >> c) & 1u) ? tf32_rna(e00) : 0u;
            p0.y = ((mm0 >> (c + 1)) & 1u) ? tf32_rna(e01) : 0u;
            p1.x = ((mm1 >> c) & 1u) ? tf32_rna(e10) : 0u;
            p1.y = ((mm1 >> (c + 1)) & 1u) ? tf32_rna(e11) : 0u;
            *(uint2*)(Ps + r0 * PS_STR + c) = p0;
            *(uint2*)(Ps + r1 * PS_STR + c) = p1;
        }
        rs0 += __shfl_xor_sync(0xffffffffu, rs0, 1);
        rs0 += __shfl_xor_sync(0xffffffffu, rs0, 2);
        rs1 += __shfl_xor_sync(0xffffffffu, rs1, 1);
        rs1 += __shfl_xor_sync(0xffffffffu, rs1, 2);
        l0 = l0 * fr0 + rs0; m0 = mn0;
        l1 = l1 * fr1 + rs1; m1 = mn1;

        // rescale O
#pragma unroll
        for (int nt = 0; nt < 16; nt++) {
            O[nt][0] *= fr0; O[nt][1] *= fr0;
            O[nt][2] *= fr1; O[nt][3] *= fr1;
        }
        __syncwarp();   // P tile rows are warp-private; make stores visible

        // ---- gemm2: O[16,128] += P[16,64] V[64,128], single-pass tf32 ----
#pragma unroll 1
        for (int ks = 0; ks < 8; ks++) {
            const int kr = ks * 8 + tig;
            uint32_t pa[4];
            pa[0] = Ps[r0 * PS_STR + kr];
            pa[1] = Ps[r1 * PS_STR + kr];
            pa[2] = Ps[r0 * PS_STR + kr + 4];
            pa[3] = Ps[r1 * PS_STR + kr + 4];
#pragma unroll
            for (int nt = 0; nt < 16; nt++) {
                uint32_t vb0 = Vs[kr * VS_STR + nt * 8 + g];
                uint32_t vb1 = Vs[(kr + 4) * VS_STR + nt * 8 + g];
                mma_tf32(O[nt], pa, vb0, vb1);
            }
        }
    }

    // ---- epilogue ----
    const float inv0 = 1.f / (l0 * 0.7f);
    const float inv1 = 1.f / (l1 * 0.7f);
    float* o0 = out + ((size_t)b * SS + gi0) * DD;
    float* o1 = out + ((size_t)b * SS + gi1) * DD;
#pragma unroll
    for (int nt = 0; nt < 16; nt++) {
        const int c = nt * 8 + 2 * tig;
        *(float2*)(o0 + c) = make_float2(O[nt][0] * inv0, O[nt][1] * inv0);
        *(float2*)(o1 + c) = make_float2(O[nt][2] * inv1, O[nt][3] * inv1);
    }
}

// ---------------------------------------------------------------------------
extern "C" void kernel_launch(void* const* d_in, const int* in_sizes, int n_in,
                              void* d_out, int out_size) {
    (void)in_sizes; (void)n_in; (void)out_size;
    const float* q = (const float*)d_in[0];
    const float* k = (const float*)d_in[1];
    const float* v = (const float*)d_in[2];
    const float* scale = (const float*)d_in[3];
    float* out = (float*)d_out;

    static const bool _init = []() {
        cudaFuncSetAttribute(attn_mma,
                             cudaFuncAttributeMaxDynamicSharedMemorySize,
                             SMEM_BYTES);
        return true;
    }();
    (void)_init;

    mask_kernel<<<(1 << 22) / NTH, NTH>>>();
    dim3 grid(SS / BQ, BB);
    attn_mma<<<grid, NTH, SMEM_BYTES>>>(q, k, v, scale, out);
}